// round 7
// baseline (speedup 1.0000x reference)
#include <cuda_runtime.h>
#include <cuda_bf16.h>
#include <math_constants.h>
#include <cstdint>

// Fixed shapes: b=2,h=16,s=4096,d=64,m=256
constexpr int D        = 64;
constexpr int M        = 256;
constexpr int TOKENS   = 2 * 16 * 4096;    // 131072 per tensor
constexpr int TPB_TOK  = 64;               // tokens per tile
constexpr int NTILES   = TOKENS / TPB_TOK; // 2048 per tensor
constexpr int NSLABS   = 32;               // (b,h) slabs
constexpr int TPS      = 64;               // tiles per slab
constexpr float NORMALIZER = 0.35355339059327379f; // 64^-0.25
constexpr float HALF_N2    = 0.0625f;      // 0.5 * normalizer^2
constexpr float RATIO      = 0.0625f;      // 256^-0.5
constexpr float EPSV       = 1e-4f;
constexpr float OFFSET     = RATIO * EPSV;
constexpr float L2E        = 1.4426950408889634f;
constexpr float LOG2RATIO  = -4.0f;        // log2(1/16)

// Work-item space: slab-major. Per slab: 64 k-tiles, 64 q-tiles,
// 64 rescale chunks of slab (j-2). Tail: rescale of slabs 30,31.
constexpr int IPS        = 192;            // items per slab
constexpr int ITEMS_MAIN = NSLABS * IPS;   // 6144
constexpr int NITEMS     = ITEMS_MAIN + 2 * TPS;  // 6272
constexpr int SLAB_FLTS  = 4096 * 256;     // 1,048,576 floats per slab
constexpr int CHUNK_FLTS = SLAB_FLTS / 64; // 16384 floats per rescale chunk

// smem layout (offsets from 1024-aligned base)
constexpr int SM_B_HI = 0;        // 256 x 128B (bf16 hi of proj*normalizer, sw128)
constexpr int SM_B_LO = 32768;    // 256 x 128B
constexpr int SM_A_HI = 65536;    // 64 x 128B
constexpr int SM_A_LO = 73728;    // 64 x 128B
constexpr int SM_RAW  = 81920;    // 16KB raw fp32 A staging (cp.async target)
constexpr int SM_DIAG = 98304;    // 64 f32
constexpr int SM_SMAX = 98560;    // 4 x 64 f32
constexpr int SM_SWARP= 99584;    // 8 f32
constexpr int SMEM_BYTES = 99616 + 1024;

__device__ float g_stab[NSLABS];
__device__ int   g_kdone[NSLABS];
__device__ uint4 g_Bimg[4096];    // 64KB pre-swizzled bf16 hi/lo image of B

__device__ __forceinline__ void atomicMaxFloat(float* addr, float val) {
    int* ai = (int*)addr;
    int old = *ai;
    while (__int_as_float(old) < val) {
        int assumed = old;
        old = atomicCAS(ai, assumed, __float_as_int(val));
        if (old == assumed) break;
    }
}
__device__ __forceinline__ uint32_t smem_u32(const void* p) {
    uint32_t a;
    asm("{ .reg .u64 t; cvta.to.shared.u64 t, %1; cvt.u32.u64 %0, t; }"
        : "=r"(a) : "l"(p));
    return a;
}
__device__ __forceinline__ uint32_t sw128(uint32_t off) {
    return off ^ ((off >> 3) & 0x70);
}
__device__ __forceinline__ void ldm_x4(uint32_t* r, uint32_t addr) {
    asm volatile("ldmatrix.sync.aligned.m8n8.x4.shared.b16 {%0,%1,%2,%3}, [%4];"
                 : "=r"(r[0]), "=r"(r[1]), "=r"(r[2]), "=r"(r[3]) : "r"(addr));
}
__device__ __forceinline__ void mma16816(float* c, const uint32_t* a,
                                         uint32_t b0, uint32_t b1) {
    asm volatile(
        "mma.sync.aligned.m16n8k16.row.col.f32.bf16.bf16.f32 "
        "{%0,%1,%2,%3}, {%4,%5,%6,%7}, {%8,%9}, {%0,%1,%2,%3};"
        : "+f"(c[0]), "+f"(c[1]), "+f"(c[2]), "+f"(c[3])
        : "r"(a[0]), "r"(a[1]), "r"(a[2]), "r"(a[3]), "r"(b0), "r"(b1));
}
__device__ __forceinline__ float ex2(float x) {
    float r;
    asm("ex2.approx.f32 %0, %1;" : "=f"(r) : "f"(x));
    return r;
}
__device__ __forceinline__ void cp_async16(uint32_t smem_dst, const void* gsrc) {
    asm volatile("cp.async.cg.shared.global [%0], [%1], 16;"
                 :: "r"(smem_dst), "l"(gsrc) : "memory");
}
__device__ __forceinline__ void cp_commit() {
    asm volatile("cp.async.commit_group;" ::: "memory");
}
__device__ __forceinline__ void cp_wait0() {
    asm volatile("cp.async.wait_group 0;" ::: "memory");
}
__device__ __forceinline__ uint32_t pack_bf16x2(float a, float b) {
    __nv_bfloat162 t = __floats2bfloat162_rn(a, b);
    return *reinterpret_cast<uint32_t*>(&t);
}
__device__ __forceinline__ void split_f4(float4 v, uint2& hi, uint2& lo) {
    float hx = __bfloat162float(__float2bfloat16(v.x));
    float hy = __bfloat162float(__float2bfloat16(v.y));
    float hz = __bfloat162float(__float2bfloat16(v.z));
    float hw = __bfloat162float(__float2bfloat16(v.w));
    hi.x = pack_bf16x2(hx, hy);
    hi.y = pack_bf16x2(hz, hw);
    lo.x = pack_bf16x2(v.x - hx, v.y - hy);
    lo.y = pack_bf16x2(v.z - hz, v.w - hw);
}

// Item decode: returns tile index [0,2048) or -1; isQ set for q tiles.
__device__ __forceinline__ int decode_tile(int i, bool& isQ) {
    if (i >= ITEMS_MAIN) return -1;
    int r = i % IPS;
    if (r >= 128) return -1;
    isQ = (r >= 64);
    return (i / IPS) * TPS + (r & 63);
}

// Parallel one-shot prep: 16 blocks. Block 0 also resets stab/kdone.
__global__ void prep_B(const float* __restrict__ proj) {
    int tid = threadIdx.x;
    if (blockIdx.x == 0 && tid < NSLABS) {
        g_stab[tid]  = -CUDART_INF_F;
        g_kdone[tid] = 0;
    }
    char* dst = reinterpret_cast<char*>(g_Bimg);
    int flat = tid + 256 * blockIdx.x;       // row = flat>>4, c4 = flat&15
    float4 v = reinterpret_cast<const float4*>(proj)[flat];
    v.x *= NORMALIZER; v.y *= NORMALIZER; v.z *= NORMALIZER; v.w *= NORMALIZER;
    uint2 hi, lo; split_f4(v, hi, lo);
    uint32_t sw = sw128((uint32_t)(flat >> 4) * 128u + (uint32_t)(flat & 15) * 8u);
    *reinterpret_cast<uint2*>(dst + sw)          = hi;
    *reinterpret_cast<uint2*>(dst + 32768u + sw) = lo;
}

// Persistent fused kernel over the slab-major work-item queue.
// Warp wid: rg = wid&1 -> rows 32*rg..+31; ch = wid>>1 -> cols 64*ch..+63.
__global__ __launch_bounds__(256, 2) void proj_fused(
    const float* __restrict__ qdat,
    const float* __restrict__ kdat,
    float* __restrict__ out_q,
    float* __restrict__ out_k)
{
    extern __shared__ char smraw[];
    char* sm = (char*)(((uintptr_t)smraw + 1023) & ~(uintptr_t)1023);
    const uint32_t s0 = smem_u32(sm);
    const int tid = threadIdx.x, lane = tid & 31, wid = tid >> 5;
    const int rg = wid & 1, ch = wid >> 1;
    const int grid = gridDim.x;

    // ---- copy pre-swizzled B image (64KB) into smem once
    {
        uint4* smB = reinterpret_cast<uint4*>(sm + SM_B_HI);
        #pragma unroll
        for (int i = 0; i < 16; ++i) smB[tid + 256 * i] = g_Bimg[tid + 256 * i];
    }

    // ---- hoisted ldmatrix addresses
    const int arowoff = lane & 15;
    const int akoff   = (lane & 16);
    const int browoff = ((lane & 16) >> 1) + (lane & 7);
    const int bkoff   = (lane & 8) * 2;
    uint32_t aaddr[2][4], bhaddr[4], bladdr[4];
    #pragma unroll
    for (int ks = 0; ks < 4; ++ks) {
        #pragma unroll
        for (int mt = 0; mt < 2; ++mt)
            aaddr[mt][ks] = s0 + SM_A_HI + sw128(
                (uint32_t)(32*rg + 16*mt + arowoff) * 128u + (uint32_t)(ks*32 + akoff));
        uint32_t bsw = sw128((uint32_t)browoff * 128u + (uint32_t)(ks*32 + bkoff));
        bhaddr[ks] = s0 + SM_B_HI + (uint32_t)ch * 8192u + bsw;
        bladdr[ks] = s0 + SM_B_LO + (uint32_t)ch * 8192u + bsw;
    }
    const int g = lane >> 2, t = lane & 3;
    float* sdiag = reinterpret_cast<float*>(sm + SM_DIAG);
    float* smax  = reinterpret_cast<float*>(sm + SM_SMAX);
    float* swarp = reinterpret_cast<float*>(sm + SM_SWARP);
    float4* raw  = reinterpret_cast<float4*>(sm + SM_RAW);
    const uint32_t raw0 = s0 + SM_RAW;

    // ---- prefetch for first item if it's a GEMM tile
    int pref = -1;
    {
        bool isQ;
        int dt = decode_tile(blockIdx.x, isQ);
        if (dt >= 0) {
            const float4* x4 = reinterpret_cast<const float4*>(isQ ? qdat : kdat)
                             + (size_t)dt * TPB_TOK * (D / 4);
            #pragma unroll
            for (int i2 = 0; i2 < 4; ++i2) {
                int flat = tid + 256 * i2;
                cp_async16(raw0 + (uint32_t)flat * 16u, x4 + flat);
            }
            cp_commit();
            pref = blockIdx.x;
        }
    }

    for (int item = blockIdx.x; item < NITEMS; item += grid) {
        bool isQ;
        const int dtile = decode_tile(item, isQ);

        if (dtile >= 0) {
            // ================= GEMM tile item =================
            if (pref != item) {
                const float4* x4 = reinterpret_cast<const float4*>(isQ ? qdat : kdat)
                                 + (size_t)dtile * TPB_TOK * (D / 4);
                #pragma unroll
                for (int i2 = 0; i2 < 4; ++i2) {
                    int flat = tid + 256 * i2;
                    cp_async16(raw0 + (uint32_t)flat * 16u, x4 + flat);
                }
                cp_commit();
            }
            cp_wait0();
            __syncthreads();   // prev item done with A smem + sdiag; raw ready

            // convert raw -> bf16 hi/lo A tiles + diag
            #pragma unroll
            for (int i2 = 0; i2 < 4; ++i2) {
                int flat = tid + 256 * i2;      // token = flat>>4
                float4 v = raw[flat];
                float sq = v.x*v.x + v.y*v.y + v.z*v.z + v.w*v.w;
                sq += __shfl_down_sync(0xffffffffu, sq, 8, 16);
                sq += __shfl_down_sync(0xffffffffu, sq, 4, 16);
                sq += __shfl_down_sync(0xffffffffu, sq, 2, 16);
                sq += __shfl_down_sync(0xffffffffu, sq, 1, 16);
                if ((tid & 15) == 0) sdiag[flat >> 4] = HALF_N2 * sq;
                uint2 hi, lo; split_f4(v, hi, lo);
                uint32_t sw = sw128((uint32_t)(flat >> 4) * 128u + (uint32_t)(flat & 15) * 8u);
                *reinterpret_cast<uint2*>(sm + SM_A_HI + sw) = hi;
                *reinterpret_cast<uint2*>(sm + SM_A_LO + sw) = lo;
            }
            __syncthreads();   // A smem + sdiag visible; raw free

            // prefetch next GEMM item (scan 2 candidates)
            pref = -1;
            #pragma unroll
            for (int cstep = 1; cstep <= 2; ++cstep) {
                int cand = item + cstep * grid;
                if (pref < 0 && cand < NITEMS) {
                    bool cq;
                    int cdt = decode_tile(cand, cq);
                    if (cdt >= 0) {
                        const float4* x4 = reinterpret_cast<const float4*>(cq ? qdat : kdat)
                                         + (size_t)cdt * TPB_TOK * (D / 4);
                        #pragma unroll
                        for (int i2 = 0; i2 < 4; ++i2) {
                            int flat = tid + 256 * i2;
                            cp_async16(raw0 + (uint32_t)flat * 16u, x4 + flat);
                        }
                        pref = cand;
                    }
                }
            }
            cp_commit();

            // GEMM: 3 product phases per k-step
            float acc[2][8][4];
            #pragma unroll
            for (int mt = 0; mt < 2; ++mt)
                #pragma unroll
                for (int nt = 0; nt < 8; ++nt)
                    #pragma unroll
                    for (int j = 0; j < 4; ++j) acc[mt][nt][j] = 0.0f;

            #pragma unroll
            for (int ks = 0; ks < 4; ++ks) {
                uint32_t ah[2][4], al[2][4];
                ldm_x4(ah[0], aaddr[0][ks]);
                ldm_x4(ah[1], aaddr[1][ks]);
                ldm_x4(al[0], aaddr[0][ks] + 8192u);
                ldm_x4(al[1], aaddr[1][ks] + 8192u);
                #pragma unroll
                for (int np = 0; np < 4; ++np) {
                    uint32_t b[4];
                    ldm_x4(b, bhaddr[ks] + (uint32_t)np * 2048u);
                    #pragma unroll
                    for (int mt = 0; mt < 2; ++mt) {
                        mma16816(acc[mt][2*np],   ah[mt], b[0], b[1]);
                        mma16816(acc[mt][2*np+1], ah[mt], b[2], b[3]);
                    }
                }
                #pragma unroll
                for (int np = 0; np < 4; ++np) {
                    uint32_t b[4];
                    ldm_x4(b, bladdr[ks] + (uint32_t)np * 2048u);
                    #pragma unroll
                    for (int mt = 0; mt < 2; ++mt) {
                        mma16816(acc[mt][2*np],   ah[mt], b[0], b[1]);
                        mma16816(acc[mt][2*np+1], ah[mt], b[2], b[3]);
                    }
                }
                #pragma unroll
                for (int np = 0; np < 4; ++np) {
                    uint32_t b[4];
                    ldm_x4(b, bhaddr[ks] + (uint32_t)np * 2048u);
                    #pragma unroll
                    for (int mt = 0; mt < 2; ++mt) {
                        mma16816(acc[mt][2*np],   al[mt], b[0], b[1]);
                        mma16816(acc[mt][2*np+1], al[mt], b[2], b[3]);
                    }
                }
            }

            // epilogue. Fragment rows: g (+8); cols: nt*8 + 2*t.
            const long long tok0 = (long long)dtile * TPB_TOK;
            float cb[2][2];

            if (isQ) {
                #pragma unroll
                for (int mt = 0; mt < 2; ++mt) {
                    float m0 = -CUDART_INF_F, m1 = -CUDART_INF_F;
                    #pragma unroll
                    for (int nt = 0; nt < 8; ++nt) {
                        m0 = fmaxf(m0, fmaxf(acc[mt][nt][0], acc[mt][nt][1]));
                        m1 = fmaxf(m1, fmaxf(acc[mt][nt][2], acc[mt][nt][3]));
                    }
                    m0 = fmaxf(m0, __shfl_xor_sync(0xffffffffu, m0, 1));
                    m0 = fmaxf(m0, __shfl_xor_sync(0xffffffffu, m0, 2));
                    m1 = fmaxf(m1, __shfl_xor_sync(0xffffffffu, m1, 1));
                    m1 = fmaxf(m1, __shfl_xor_sync(0xffffffffu, m1, 2));
                    if (t == 0) {
                        smax[ch * 64 + 32*rg + 16*mt + g]     = m0;
                        smax[ch * 64 + 32*rg + 16*mt + g + 8] = m1;
                    }
                }
                __syncthreads();
                #pragma unroll
                for (int mt = 0; mt < 2; ++mt)
                    #pragma unroll
                    for (int h = 0; h < 2; ++h) {
                        int r = 32*rg + 16*mt + g + 8*h;
                        float mm = fmaxf(fmaxf(smax[r], smax[64 + r]),
                                         fmaxf(smax[128 + r], smax[192 + r]));
                        cb[mt][h] = LOG2RATIO - (sdiag[r] + mm) * L2E;
                    }
                #pragma unroll
                for (int mt = 0; mt < 2; ++mt) {
                    const int r0 = 32*rg + 16*mt + g;
                    float* o0 = out_q + (tok0 + r0) * M + 64*ch + 2*t;
                    float* o1 = out_q + (tok0 + r0 + 8) * M + 64*ch + 2*t;
                    #pragma unroll
                    for (int nt = 0; nt < 8; ++nt) {
                        float2 e0, e1;
                        e0.x = ex2(fmaf(acc[mt][nt][0], L2E, cb[mt][0])) + OFFSET;
                        e0.y = ex2(fmaf(acc[mt][nt][1], L2E, cb[mt][0])) + OFFSET;
                        e1.x = ex2(fmaf(acc[mt][nt][2], L2E, cb[mt][1])) + OFFSET;
                        e1.y = ex2(fmaf(acc[mt][nt][3], L2E, cb[mt][1])) + OFFSET;
                        *reinterpret_cast<float2*>(o0 + nt * 8) = e0;
                        *reinterpret_cast<float2*>(o1 + nt * 8) = e1;
                    }
                }
            } else {
                // K: store E = exp(dash - diag), track max(dash), arrive on slab
                float mx = -CUDART_INF_F;
                #pragma unroll
                for (int mt = 0; mt < 2; ++mt)
                    #pragma unroll
                    for (int h = 0; h < 2; ++h)
                        cb[mt][h] = -sdiag[32*rg + 16*mt + g + 8*h] * L2E;
                #pragma unroll
                for (int mt = 0; mt < 2; ++mt) {
                    const int r0 = 32*rg + 16*mt + g;
                    float* o0 = out_k + (tok0 + r0) * M + 64*ch + 2*t;
                    float* o1 = out_k + (tok0 + r0 + 8) * M + 64*ch + 2*t;
                    #pragma unroll
                    for (int nt = 0; nt < 8; ++nt) {
                        float2 e0, e1;
                        mx = fmaxf(mx, fmaxf(fmaxf(acc[mt][nt][0], acc[mt][nt][1]),
                                             fmaxf(acc[mt][nt][2], acc[mt][nt][3])));
                        e0.x = ex2(fmaf(acc[mt][nt][0], L2E, cb[mt][0]));
                        e0.y = ex2(fmaf(acc[mt][nt][1], L2E, cb[mt][0]));
                        e1.x = ex2(fmaf(acc[mt][nt][2], L2E, cb[mt][1]));
                        e1.y = ex2(fmaf(acc[mt][nt][3], L2E, cb[mt][1]));
                        *reinterpret_cast<float2*>(o0 + nt * 8) = e0;
                        *reinterpret_cast<float2*>(o1 + nt * 8) = e1;
                    }
                }
                #pragma unroll
                for (int off = 16; off; off >>= 1)
                    mx = fmaxf(mx, __shfl_xor_sync(0xffffffffu, mx, off));
                if (lane == 0) swarp[wid] = mx;
                __syncthreads();
                if (tid == 0) {
                    float mm = swarp[0];
                    #pragma unroll
                    for (int w = 1; w < 8; ++w) mm = fmaxf(mm, swarp[w]);
                    const int slab = dtile >> 6;
                    atomicMaxFloat(&g_stab[slab], mm);
                    __threadfence();             // release E stores + stab
                    atomicAdd(&g_kdone[slab], 1);
                }
            }
        } else {
            // ================= rescale chunk item (or noop) =================
            int rslab, rchunk;
            if (item >= ITEMS_MAIN) {
                int tt = item - ITEMS_MAIN;
                rslab = 30 + (tt >> 6);
                rchunk = tt & 63;
            } else {
                int slab = item / IPS, r = item % IPS;
                if (slab < 2) continue;          // noop
                rslab = slab - 2;
                rchunk = r - 128;
            }
            // acquire: slab's 64 k-tiles complete
            const volatile int* kd = (const volatile int*)&g_kdone[rslab];
            while (*kd != TPS) __nanosleep(128);
            __threadfence();
            float stab = *(volatile float*)&g_stab[rslab];
            float scale = RATIO * __expf(-stab);
            float4* p = reinterpret_cast<float4*>(
                out_k + (size_t)rslab * SLAB_FLTS + (size_t)rchunk * CHUNK_FLTS);
            #pragma unroll 4
            for (int u = 0; u < 16; ++u) {
                float4 v = p[tid + 256 * u];
                v.x = fmaf(scale, v.x, OFFSET);
                v.y = fmaf(scale, v.y, OFFSET);
                v.z = fmaf(scale, v.z, OFFSET);
                v.w = fmaf(scale, v.w, OFFSET);
                p[tid + 256 * u] = v;
            }
        }
    }
}

extern "C" void kernel_launch(void* const* d_in, const int* in_sizes, int n_in,
                              void* d_out, int out_size) {
    const float* q    = (const float*)d_in[0];
    const float* k    = (const float*)d_in[1];
    const float* proj = (const float*)d_in[2];

    float* out_q = (float*)d_out;
    float* out_k = out_q + (long long)TOKENS * M;

    cudaFuncSetAttribute(proj_fused, cudaFuncAttributeMaxDynamicSharedMemorySize, SMEM_BYTES);

    // Residency-safe persistent grid (spin-wait requires all CTAs resident).
    int sms = 0;
    cudaDeviceGetAttribute(&sms, cudaDevAttrMultiProcessorCount, 0);
    int maxb = 0;
    cudaOccupancyMaxActiveBlocksPerMultiprocessor(&maxb, proj_fused, 256, SMEM_BYTES);
    if (maxb < 1) maxb = 1;
    if (maxb > 2) maxb = 2;
    int grid = sms * maxb;

    prep_B<<<16, 256>>>(proj);
    proj_fused<<<grid, 256, SMEM_BYTES>>>(q, k, out_q, out_k);
}

// round 8
// speedup vs baseline: 1.0440x; 1.0440x over previous
#include <cuda_runtime.h>
#include <cuda_bf16.h>
#include <math_constants.h>
#include <cstdint>

// Fixed shapes: b=2,h=16,s=4096,d=64,m=256
constexpr int D        = 64;
constexpr int M        = 256;
constexpr int TOKENS   = 2 * 16 * 4096;    // 131072 per tensor
constexpr int TPB_TOK  = 64;               // tokens per tile
constexpr int NTILES   = TOKENS / TPB_TOK; // 2048 per tensor
constexpr int GRID_P   = 304;              // 2 CTAs/SM persistent (152 SMs)
constexpr float NORMALIZER = 0.35355339059327379f; // 64^-0.25
constexpr float HALF_N2    = 0.0625f;      // 0.5 * normalizer^2
constexpr float RATIO      = 0.0625f;      // 256^-0.5
constexpr float EPSV       = 1e-4f;
constexpr float OFFSET     = RATIO * EPSV;
constexpr float L2E        = 1.4426950408889634f;
constexpr float LOG2RATIO  = -4.0f;        // log2(1/16)

// smem layout (offsets from 1024-aligned base)
constexpr int SM_B_HI = 0;        // 256 x 128B (bf16 hi of proj*normalizer, sw128)
constexpr int SM_B_LO = 32768;    // 256 x 128B  (= SM_B_HI + 32768)
constexpr int SM_A_HI = 65536;    // 64 x 128B
constexpr int SM_A_LO = 73728;    // 64 x 128B   (= SM_A_HI + 8192)
constexpr int SM_RAW  = 81920;    // 16KB raw fp32 A staging (cp.async target)
constexpr int SM_DIAG = 98304;    // 64 f32
constexpr int SM_SMAX = 98560;    // 4 x 64 f32
constexpr int SM_SWARP= 99584;    // 8 f32
constexpr int SMEM_BYTES = 99616 + 1024;

__device__ float g_stab[32];
__device__ uint4 g_Bimg[4096];    // 64KB pre-swizzled bf16 hi/lo image of B

__device__ __forceinline__ void atomicMaxFloat(float* addr, float val) {
    int* ai = (int*)addr;
    int old = *ai;
    while (__int_as_float(old) < val) {
        int assumed = old;
        old = atomicCAS(ai, assumed, __float_as_int(val));
        if (old == assumed) break;
    }
}
__device__ __forceinline__ uint32_t smem_u32(const void* p) {
    uint32_t a;
    asm("{ .reg .u64 t; cvta.to.shared.u64 t, %1; cvt.u32.u64 %0, t; }"
        : "=r"(a) : "l"(p));
    return a;
}
__device__ __forceinline__ uint32_t sw128(uint32_t off) {
    return off ^ ((off >> 3) & 0x70);
}
__device__ __forceinline__ void ldm_x4(uint32_t* r, uint32_t addr) {
    asm volatile("ldmatrix.sync.aligned.m8n8.x4.shared.b16 {%0,%1,%2,%3}, [%4];"
                 : "=r"(r[0]), "=r"(r[1]), "=r"(r[2]), "=r"(r[3]) : "r"(addr));
}
__device__ __forceinline__ void mma16816(float* c, const uint32_t* a,
                                         uint32_t b0, uint32_t b1) {
    asm volatile(
        "mma.sync.aligned.m16n8k16.row.col.f32.bf16.bf16.f32 "
        "{%0,%1,%2,%3}, {%4,%5,%6,%7}, {%8,%9}, {%0,%1,%2,%3};"
        : "+f"(c[0]), "+f"(c[1]), "+f"(c[2]), "+f"(c[3])
        : "r"(a[0]), "r"(a[1]), "r"(a[2]), "r"(a[3]), "r"(b0), "r"(b1));
}
__device__ __forceinline__ float ex2(float x) {
    float r;
    asm("ex2.approx.f32 %0, %1;" : "=f"(r) : "f"(x));
    return r;
}
__device__ __forceinline__ void cp_async16(uint32_t smem_dst, const void* gsrc) {
    asm volatile("cp.async.cg.shared.global [%0], [%1], 16;"
                 :: "r"(smem_dst), "l"(gsrc) : "memory");
}
__device__ __forceinline__ void cp_commit() {
    asm volatile("cp.async.commit_group;" ::: "memory");
}
__device__ __forceinline__ void cp_wait0() {
    asm volatile("cp.async.wait_group 0;" ::: "memory");
}
__device__ __forceinline__ uint32_t pack_bf16x2(float a, float b) {
    __nv_bfloat162 t = __floats2bfloat162_rn(a, b);
    return *reinterpret_cast<uint32_t*>(&t);
}
__device__ __forceinline__ void split_f4(float4 v, uint2& hi, uint2& lo) {
    float hx = __bfloat162float(__float2bfloat16(v.x));
    float hy = __bfloat162float(__float2bfloat16(v.y));
    float hz = __bfloat162float(__float2bfloat16(v.z));
    float hw = __bfloat162float(__float2bfloat16(v.w));
    hi.x = pack_bf16x2(hx, hy);
    hi.y = pack_bf16x2(hz, hw);
    lo.x = pack_bf16x2(v.x - hx, v.y - hy);
    lo.y = pack_bf16x2(v.z - hz, v.w - hw);
}

// Parallel one-shot prep: 16 blocks build the B image; block 0 resets stab.
__global__ void prep_B(const float* __restrict__ proj) {
    int tid = threadIdx.x;
    if (blockIdx.x == 0 && tid < 32) g_stab[tid] = -CUDART_INF_F;
    char* dst = reinterpret_cast<char*>(g_Bimg);
    int flat = tid + 256 * blockIdx.x;       // row = flat>>4, c4 = flat&15
    float4 v = reinterpret_cast<const float4*>(proj)[flat];
    v.x *= NORMALIZER; v.y *= NORMALIZER; v.z *= NORMALIZER; v.w *= NORMALIZER;
    uint2 hi, lo; split_f4(v, hi, lo);
    uint32_t sw = sw128((uint32_t)(flat >> 4) * 128u + (uint32_t)(flat & 15) * 8u);
    *reinterpret_cast<uint2*>(dst + sw)          = hi;
    *reinterpret_cast<uint2*>(dst + 32768u + sw) = lo;
}

// Fused persistent kernel: tiles [0,2048) = q, [2048,4096) = k.
// Warp wid: rg = wid&1 -> rows 32*rg..+31; ch = wid>>1 -> cols 64*ch..+63.
__global__ __launch_bounds__(256, 2) void proj_fused(
    const float* __restrict__ qdat,
    const float* __restrict__ kdat,
    float* __restrict__ out_q,
    float* __restrict__ out_k)
{
    extern __shared__ char smraw[];
    char* sm = (char*)(((uintptr_t)smraw + 1023) & ~(uintptr_t)1023);
    const uint32_t s0 = smem_u32(sm);
    const int tid = threadIdx.x, lane = tid & 31, wid = tid >> 5;
    const int rg = wid & 1, ch = wid >> 1;

    // ---- copy pre-swizzled B image (64KB) into smem once
    {
        uint4* smB = reinterpret_cast<uint4*>(sm + SM_B_HI);
        #pragma unroll
        for (int i = 0; i < 16; ++i) smB[tid + 256 * i] = g_Bimg[tid + 256 * i];
    }

    // ---- hoisted ldmatrix addresses (minimal register footprint)
    const int arowoff = lane & 15;
    const int akoff   = (lane & 16);
    const int browoff = ((lane & 16) >> 1) + (lane & 7);
    const int bkoff   = (lane & 8) * 2;
    uint32_t aaddr[2][4], bhaddr[4];
    #pragma unroll
    for (int ks = 0; ks < 4; ++ks) {
        #pragma unroll
        for (int mt = 0; mt < 2; ++mt)
            aaddr[mt][ks] = s0 + SM_A_HI + sw128(
                (uint32_t)(32*rg + 16*mt + arowoff) * 128u + (uint32_t)(ks*32 + akoff));
        bhaddr[ks] = s0 + SM_B_HI + (uint32_t)ch * 8192u
                   + sw128((uint32_t)browoff * 128u + (uint32_t)(ks*32 + bkoff));
    }
    const int g = lane >> 2, t = lane & 3;
    float* sdiag = reinterpret_cast<float*>(sm + SM_DIAG);
    float* smax  = reinterpret_cast<float*>(sm + SM_SMAX);
    float* swarp = reinterpret_cast<float*>(sm + SM_SWARP);
    float4* raw  = reinterpret_cast<float4*>(sm + SM_RAW);
    const uint32_t raw0 = s0 + SM_RAW;

    // ---- prefetch first tile's raw A via cp.async
    {
        const float* src = (blockIdx.x < NTILES) ? qdat : kdat;
        int dtile = (blockIdx.x < NTILES) ? blockIdx.x : blockIdx.x - NTILES;
        const float4* x4 = reinterpret_cast<const float4*>(src)
                         + (size_t)dtile * TPB_TOK * (D / 4);
        #pragma unroll
        for (int i = 0; i < 4; ++i) {
            int flat = tid + 256 * i;
            cp_async16(raw0 + (uint32_t)flat * 16u, x4 + flat);
        }
        cp_commit();
    }

    for (int tile = blockIdx.x; tile < 2 * NTILES; tile += GRID_P) {
        const bool isQ = tile < NTILES;
        const int dtile = isQ ? tile : tile - NTILES;
        float* out = isQ ? out_q : out_k;

        cp_wait0();
        __syncthreads();   // prev iter's GEMM/epilogue done with A smem + sdiag

        // ---- convert raw -> bf16 hi/lo A tiles + diag
        #pragma unroll
        for (int i = 0; i < 4; ++i) {
            int flat = tid + 256 * i;          // token = flat>>4
            float4 v = raw[flat];
            float sq = v.x*v.x + v.y*v.y + v.z*v.z + v.w*v.w;
            sq += __shfl_down_sync(0xffffffffu, sq, 8, 16);
            sq += __shfl_down_sync(0xffffffffu, sq, 4, 16);
            sq += __shfl_down_sync(0xffffffffu, sq, 2, 16);
            sq += __shfl_down_sync(0xffffffffu, sq, 1, 16);
            if ((tid & 15) == 0) sdiag[flat >> 4] = HALF_N2 * sq;
            uint2 hi, lo; split_f4(v, hi, lo);
            uint32_t sw = sw128((uint32_t)(flat >> 4) * 128u + (uint32_t)(flat & 15) * 8u);
            *reinterpret_cast<uint2*>(sm + SM_A_HI + sw) = hi;
            *reinterpret_cast<uint2*>(sm + SM_A_LO + sw) = lo;
        }
        __syncthreads();   // A smem + sdiag visible; raw free for next prefetch

        // ---- prefetch next tile's raw A (overlaps with GEMM + epilogue)
        {
            int ntile = tile + GRID_P;
            if (ntile < 2 * NTILES) {
                const float* src = (ntile < NTILES) ? qdat : kdat;
                int ndt = (ntile < NTILES) ? ntile : ntile - NTILES;
                const float4* x4 = reinterpret_cast<const float4*>(src)
                                 + (size_t)ndt * TPB_TOK * (D / 4);
                #pragma unroll
                for (int i = 0; i < 4; ++i) {
                    int flat = tid + 256 * i;
                    cp_async16(raw0 + (uint32_t)flat * 16u, x4 + flat);
                }
            }
            cp_commit();
        }

        // ---- GEMM. Per ks: bh cached in regs (used by phases 1 and 3),
        //      bl double-buffered, al hoisted before phase 2.
        float acc[2][8][4];
        #pragma unroll
        for (int mt = 0; mt < 2; ++mt)
            #pragma unroll
            for (int nt = 0; nt < 8; ++nt)
                #pragma unroll
                for (int j = 0; j < 4; ++j) acc[mt][nt][j] = 0.0f;

        #pragma unroll
        for (int ks = 0; ks < 4; ++ks) {
            uint32_t ah[2][4];
            ldm_x4(ah[0], aaddr[0][ks]);
            ldm_x4(ah[1], aaddr[1][ks]);
            // load all bh fragments for this ks (cached across phases 1 and 3)
            uint32_t bh[4][4];
            #pragma unroll
            for (int np = 0; np < 4; ++np)
                ldm_x4(bh[np], bhaddr[ks] + (uint32_t)np * 2048u);

            // phase 1: ah * bh
            #pragma unroll
            for (int np = 0; np < 4; ++np) {
                #pragma unroll
                for (int mt = 0; mt < 2; ++mt) {
                    mma16816(acc[mt][2*np],   ah[mt], bh[np][0], bh[np][1]);
                    mma16816(acc[mt][2*np+1], ah[mt], bh[np][2], bh[np][3]);
                }
            }

            // hoist al loads so phase 2's mmas cover their latency
            uint32_t al[2][4];
            ldm_x4(al[0], aaddr[0][ks] + 8192u);   // A_LO mirrors A_HI at +8KB
            ldm_x4(al[1], aaddr[1][ks] + 8192u);

            // phase 2: ah * bl, double-buffered bl
            uint32_t bl[2][4];
            ldm_x4(bl[0], bhaddr[ks] + 32768u);    // B_LO mirrors B_HI at +32KB
            #pragma unroll
            for (int np = 0; np < 4; ++np) {
                if (np < 3)
                    ldm_x4(bl[(np+1)&1], bhaddr[ks] + 32768u + (uint32_t)(np+1) * 2048u);
                #pragma unroll
                for (int mt = 0; mt < 2; ++mt) {
                    mma16816(acc[mt][2*np],   ah[mt], bl[np&1][0], bl[np&1][1]);
                    mma16816(acc[mt][2*np+1], ah[mt], bl[np&1][2], bl[np&1][3]);
                }
            }

            // phase 3: al * bh (cached — no reload)
            #pragma unroll
            for (int np = 0; np < 4; ++np) {
                #pragma unroll
                for (int mt = 0; mt < 2; ++mt) {
                    mma16816(acc[mt][2*np],   al[mt], bh[np][0], bh[np][1]);
                    mma16816(acc[mt][2*np+1], al[mt], bh[np][2], bh[np][3]);
                }
            }
        }

        // ---- epilogue. Fragment rows: g (+8); cols: nt*8 + 2*t.
        const long long tok0 = (long long)dtile * TPB_TOK;
        float cb[2][2];

        if (isQ) {
            #pragma unroll
            for (int mt = 0; mt < 2; ++mt) {
                float m0 = -CUDART_INF_F, m1 = -CUDART_INF_F;
                #pragma unroll
                for (int nt = 0; nt < 8; ++nt) {
                    m0 = fmaxf(m0, fmaxf(acc[mt][nt][0], acc[mt][nt][1]));
                    m1 = fmaxf(m1, fmaxf(acc[mt][nt][2], acc[mt][nt][3]));
                }
                m0 = fmaxf(m0, __shfl_xor_sync(0xffffffffu, m0, 1));
                m0 = fmaxf(m0, __shfl_xor_sync(0xffffffffu, m0, 2));
                m1 = fmaxf(m1, __shfl_xor_sync(0xffffffffu, m1, 1));
                m1 = fmaxf(m1, __shfl_xor_sync(0xffffffffu, m1, 2));
                if (t == 0) {
                    smax[ch * 64 + 32*rg + 16*mt + g]     = m0;
                    smax[ch * 64 + 32*rg + 16*mt + g + 8] = m1;
                }
            }
            __syncthreads();
            #pragma unroll
            for (int mt = 0; mt < 2; ++mt)
                #pragma unroll
                for (int h = 0; h < 2; ++h) {
                    int r = 32*rg + 16*mt + g + 8*h;
                    float mm = fmaxf(fmaxf(smax[r], smax[64 + r]),
                                     fmaxf(smax[128 + r], smax[192 + r]));
                    cb[mt][h] = LOG2RATIO - (sdiag[r] + mm) * L2E;
                }
            #pragma unroll
            for (int mt = 0; mt < 2; ++mt) {
                const int r0 = 32*rg + 16*mt + g;
                float* o0 = out + (tok0 + r0) * M + 64*ch + 2*t;
                float* o1 = out + (tok0 + r0 + 8) * M + 64*ch + 2*t;
                #pragma unroll
                for (int nt = 0; nt < 8; ++nt) {
                    float2 e0, e1;
                    e0.x = ex2(fmaf(acc[mt][nt][0], L2E, cb[mt][0])) + OFFSET;
                    e0.y = ex2(fmaf(acc[mt][nt][1], L2E, cb[mt][0])) + OFFSET;
                    e1.x = ex2(fmaf(acc[mt][nt][2], L2E, cb[mt][1])) + OFFSET;
                    e1.y = ex2(fmaf(acc[mt][nt][3], L2E, cb[mt][1])) + OFFSET;
                    *reinterpret_cast<float2*>(o0 + nt * 8) = e0;
                    *reinterpret_cast<float2*>(o1 + nt * 8) = e1;
                }
            }
        } else {
            // K: store E = exp(dash - diag), track max(dash) for stab
            float mx = -CUDART_INF_F;
            #pragma unroll
            for (int mt = 0; mt < 2; ++mt)
                #pragma unroll
                for (int h = 0; h < 2; ++h)
                    cb[mt][h] = -sdiag[32*rg + 16*mt + g + 8*h] * L2E;
            #pragma unroll
            for (int mt = 0; mt < 2; ++mt) {
                const int r0 = 32*rg + 16*mt + g;
                float* o0 = out + (tok0 + r0) * M + 64*ch + 2*t;
                float* o1 = out + (tok0 + r0 + 8) * M + 64*ch + 2*t;
                #pragma unroll
                for (int nt = 0; nt < 8; ++nt) {
                    float2 e0, e1;
                    mx = fmaxf(mx, fmaxf(fmaxf(acc[mt][nt][0], acc[mt][nt][1]),
                                         fmaxf(acc[mt][nt][2], acc[mt][nt][3])));
                    e0.x = ex2(fmaf(acc[mt][nt][0], L2E, cb[mt][0]));
                    e0.y = ex2(fmaf(acc[mt][nt][1], L2E, cb[mt][0]));
                    e1.x = ex2(fmaf(acc[mt][nt][2], L2E, cb[mt][1]));
                    e1.y = ex2(fmaf(acc[mt][nt][3], L2E, cb[mt][1]));
                    *reinterpret_cast<float2*>(o0 + nt * 8) = e0;
                    *reinterpret_cast<float2*>(o1 + nt * 8) = e1;
                }
            }
            #pragma unroll
            for (int off = 16; off; off >>= 1)
                mx = fmaxf(mx, __shfl_xor_sync(0xffffffffu, mx, off));
            if (lane == 0) swarp[wid] = mx;
            __syncthreads();
            if (tid == 0) {
                float mm = swarp[0];
                #pragma unroll
                for (int w = 1; w < 8; ++w) mm = fmaxf(mm, swarp[w]);
                atomicMaxFloat(&g_stab[dtile >> 6], mm);  // 64 tiles per (b,h)
            }
        }
    }
}

// k pass 2: out = (ratio*exp(-stab[bh])) * E + ratio*eps  (DRAM-bound)
__global__ void finalize_k(float* __restrict__ kout) {
    constexpr long long HALF4 = (long long)TOKENS * M / 4 / 2;
    long long i = (long long)blockIdx.x * blockDim.x + threadIdx.x;
    float4* p4 = reinterpret_cast<float4*>(kout);
    #pragma unroll
    for (int h = 0; h < 2; ++h) {
        long long idx = i + h * HALF4;
        float4 v = p4[idx];
        float scale = RATIO * __expf(-g_stab[(int)(idx >> 18)]);  // 2^18 f4 per (b,h)
        v.x = fmaf(scale, v.x, OFFSET);
        v.y = fmaf(scale, v.y, OFFSET);
        v.z = fmaf(scale, v.z, OFFSET);
        v.w = fmaf(scale, v.w, OFFSET);
        p4[idx] = v;
    }
}

extern "C" void kernel_launch(void* const* d_in, const int* in_sizes, int n_in,
                              void* d_out, int out_size) {
    const float* q    = (const float*)d_in[0];
    const float* k    = (const float*)d_in[1];
    const float* proj = (const float*)d_in[2];

    float* out_q = (float*)d_out;
    float* out_k = out_q + (long long)TOKENS * M;

    cudaFuncSetAttribute(proj_fused, cudaFuncAttributeMaxDynamicSharedMemorySize, SMEM_BYTES);

    prep_B<<<16, 256>>>(proj);
    proj_fused<<<GRID_P, 256, SMEM_BYTES>>>(q, k, out_q, out_k);

    constexpr long long HALF4 = (long long)TOKENS * M / 4 / 2;
    finalize_k<<<(int)(HALF4 / 256), 256>>>(out_k);
}